// round 14
// baseline (speedup 1.0000x reference)
#include <cuda_runtime.h>
#include <math.h>

#define B_    16
#define D_    100000
#define M_    128
#define NBIN_ 25
#define NBLK_ 444                 // 148 SMs x 3 blocks -> perfect single wave
#define WPB_  8
#define WSLOTS_ (NBLK_ * WPB_)    // 3552 = 16 batches x 222 warps
#define WPBATCH_ (WSLOTS_ / B_)   // 222
#define STRIDE_ (WPBATCH_ * 8)    // 1776 docs per sweep per batch
#define NSLOT_ 27                 // padded: slot j == bin j-1; slots 0 and 26 are trash

// global accumulators — zero at module load; last block re-zeros them each
// run so every graph replay starts from identical state.
__device__ float    g_hla[B_][NBIN_];
__device__ float    g_hll[B_][NBIN_];
__device__ float    g_lsum[B_];
__device__ unsigned g_ticket;

__global__ void __launch_bounds__(256, 3)
qap_fused(const float* __restrict__ qX,
          const float* __restrict__ dXs,
          const int*   __restrict__ labels,
          float*       __restrict__ out) {
    const int tid  = threadIdx.x;
    const int lane = tid & 31;
    const int warp = tid >> 5;
    const int e    = lane & 7;   // float4 slot within row
    const int g    = lane >> 3;  // doc within quad (0..3)

    // warp-slot -> (batch, index within batch)
    const int slot = blockIdx.x * WPB_ + warp;
    const int bw   = slot & 15;          // this warp's batch
    const int widx = slot >> 4;          // 0..221

    // per-(warp,doc) private histograms: [warp][doc(8)][arr][NSLOT_]
    __shared__ float s_hist[8 * 8 * 2 * NSLOT_];   // 13.5 KB
    __shared__ float s_wl[8];
    __shared__ int   s_batch[8];
    __shared__ int   s_last;

    #pragma unroll
    for (int i = tid; i < 8 * 8 * 2 * NSLOT_; i += 256) s_hist[i] = 0.0f;
    if (lane == 0) s_batch[warp] = bw;
    __syncthreads();

    // query slices (this warp's batch) + 1/|q| via 8-lane group butterfly
    const float4* __restrict__ qf = reinterpret_cast<const float4*>(qX + bw * M_);
    const float4 q0 = qf[e], q1 = qf[e + 8], q2 = qf[e + 16], q3 = qf[e + 24];
    float qs = q0.x*q0.x + q0.y*q0.y + q0.z*q0.z + q0.w*q0.w
             + q1.x*q1.x + q1.y*q1.y + q1.z*q1.z + q1.w*q1.w
             + q2.x*q2.x + q2.y*q2.y + q2.z*q2.z + q2.w*q2.w
             + q3.x*q3.x + q3.y*q3.y + q3.z*q3.z + q3.w*q3.w;
    qs += __shfl_xor_sync(0xFFFFFFFFu, qs, 4);
    qs += __shfl_xor_sync(0xFFFFFFFFu, qs, 2);
    qs += __shfl_xor_sync(0xFFFFFFFFu, qs, 1);
    const float inv_qn = rsqrtf(qs);

    const float4* __restrict__ dv = reinterpret_cast<const float4*>(dXs + (size_t)bw * D_ * M_);
    const int*    __restrict__ lb = labels + bw * D_;

    const int docoff = g + (e & 4);      // this lane's doc within the 8-doc chunk
    const int role   = e & 3;            // 0: ha[m0], 1: ha[m1], 2: hl[m0], 3: hl[m1]
    float* const hbase = s_hist + ((warp * 8 + docoff) * 2 + (role >> 1)) * NSLOT_
                       + (role & 1) + 1;
    float labcnt = 0.0f;

    // ---------------- software-pipelined main loop (8 docs/iter) ----------------
    int d0 = widx * 8;                   // <= 1768 < D_, every warp has work
    const float4* ra = dv + (size_t)(d0 + g) * 32;
    const float4* rb = ra + 4 * 32;
    float4 a0 = __ldcs(ra + e),      a1 = __ldcs(ra + e + 8);
    float4 a2 = __ldcs(ra + e + 16), a3 = __ldcs(ra + e + 24);
    float4 b0 = __ldcs(rb + e),      b1 = __ldcs(rb + e + 8);
    float4 b2 = __ldcs(rb + e + 16), b3 = __ldcs(rb + e + 24);
    int    lab = lb[d0 + docoff];

    while (d0 < D_) {
        const int dn   = d0 + STRIDE_;
        const int dpre = (dn < D_) ? dn : 0;     // clamped prefetch (in-bounds, unused if done)
        const float4* rna = dv + (size_t)(dpre + g) * 32;
        const float4* rnb = rna + 4 * 32;

        // consume a-regs into sums, refill with next chunk's a-data
        float dota = q0.x*a0.x + q0.y*a0.y + q0.z*a0.z + q0.w*a0.w
                   + q1.x*a1.x + q1.y*a1.y + q1.z*a1.z + q1.w*a1.w
                   + q2.x*a2.x + q2.y*a2.y + q2.z*a2.z + q2.w*a2.w
                   + q3.x*a3.x + q3.y*a3.y + q3.z*a3.z + q3.w*a3.w;
        float nra  = a0.x*a0.x + a0.y*a0.y + a0.z*a0.z + a0.w*a0.w
                   + a1.x*a1.x + a1.y*a1.y + a1.z*a1.z + a1.w*a1.w
                   + a2.x*a2.x + a2.y*a2.y + a2.z*a2.z + a2.w*a2.w
                   + a3.x*a3.x + a3.y*a3.y + a3.z*a3.z + a3.w*a3.w;
        a0 = __ldcs(rna + e);      a1 = __ldcs(rna + e + 8);
        a2 = __ldcs(rna + e + 16); a3 = __ldcs(rna + e + 24);

        // consume b-regs, refill with next chunk's b-data
        float dotb = q0.x*b0.x + q0.y*b0.y + q0.z*b0.z + q0.w*b0.w
                   + q1.x*b1.x + q1.y*b1.y + q1.z*b1.z + q1.w*b1.w
                   + q2.x*b2.x + q2.y*b2.y + q2.z*b2.z + q2.w*b2.w
                   + q3.x*b3.x + q3.y*b3.y + q3.z*b3.z + q3.w*b3.w;
        float nrb  = b0.x*b0.x + b0.y*b0.y + b0.z*b0.z + b0.w*b0.w
                   + b1.x*b1.x + b1.y*b1.y + b1.z*b1.z + b1.w*b1.w
                   + b2.x*b2.x + b2.y*b2.y + b2.z*b2.z + b2.w*b2.w
                   + b3.x*b3.x + b3.y*b3.y + b3.z*b3.z + b3.w*b3.w;
        b0 = __ldcs(rnb + e);      b1 = __ldcs(rnb + e + 8);
        b2 = __ldcs(rnb + e + 16); b3 = __ldcs(rnb + e + 24);

        const int labcur = lab;
        lab = lb[dpre + docoff];

        // shuffles + epilogue run UNDER the next chunk's DRAM latency
        #pragma unroll
        for (int o = 4; o; o >>= 1) {
            dota += __shfl_xor_sync(0xFFFFFFFFu, dota, o);
            nra  += __shfl_xor_sync(0xFFFFFFFFu, nra,  o);
            dotb += __shfl_xor_sync(0xFFFFFFFFu, dotb, o);
            nrb  += __shfl_xor_sync(0xFFFFFFFFu, nrb,  o);
        }

        const float dt  = (e < 4) ? dota : dotb;
        const float nr  = (e < 4) ? nra  : nrb;
        const float sim = dt * rsqrtf(nr) * inv_qn;     // eps never binds (norms ~11)
        const float t   = (1.0f - sim) * 12.0f;
        const float mf  = floorf(t);
        const int   m0  = (int)mf;                      // in [-1, 24] for any fp edge
        const float fr  = t - mf;
        float w = (role & 1) ? fr : (1.0f - fr);
        if (role & 2) w *= (float)labcur;               // branchless label gate
        hbase[m0] += w;                                 // LDS+FADD+STS, race-free
        if (role == 0) labcnt += (float)labcur;         // doc counted once (e==0, e==4)

        d0 = dn;
    }

    #pragma unroll
    for (int o = 16; o; o >>= 1) labcnt += __shfl_xor_sync(0xFFFFFFFFu, labcnt, o);
    if (lane == 0) s_wl[warp] = labcnt;
    __syncthreads();

    // merge: each warp's 8 doc-copies -> that warp's batch bins
    // idx over [warp(8)][arr(2)][bin(25)] = 400 entries
    for (int idx = tid; idx < 8 * 2 * NBIN_; idx += 256) {
        const int w   = idx / (2 * NBIN_);
        const int rem = idx % (2 * NBIN_);
        const int arr = rem / NBIN_, n = rem % NBIN_;
        float s = 0.0f;
        #pragma unroll
        for (int d = 0; d < 8; d++)
            s += s_hist[((w * 8 + d) * 2 + arr) * NSLOT_ + n + 1];
        const int bb = s_batch[w];
        if (arr) atomicAdd(&g_hll[bb][n], s);
        else     atomicAdd(&g_hla[bb][n], s);
    }
    if (tid < 8) atomicAdd(&g_lsum[s_batch[tid]], s_wl[tid]);

    __threadfence();
    __syncthreads();
    if (tid == 0) {
        unsigned prev = atomicAdd(&g_ticket, 1u);
        s_last = (prev == NBLK_ - 1u);
    }
    __syncthreads();
    if (!s_last) return;

    // ---------------- last block: finalize + reset state ----------------
    __shared__ float f_hl[B_][NBIN_];
    __shared__ float f_ha[B_][NBIN_];
    __shared__ float f_ls[B_];

    for (int idx = tid; idx < B_ * NBIN_; idx += 256) {
        const int bb = idx / NBIN_, n = idx % NBIN_;
        f_hl[bb][n] = __ldcg(&g_hll[bb][n]);
        f_ha[bb][n] = __ldcg(&g_hla[bb][n]);
        g_hll[bb][n] = 0.0f;
        g_hla[bb][n] = 0.0f;
    }
    if (tid < B_) {
        f_ls[tid] = __ldcg(&g_lsum[tid]);
        g_lsum[tid] = 0.0f;
    }
    __syncthreads();

    float apq = 0.0f;
    if (tid < B_) {
        float cl = 0.0f, ca = 0.0f, s = 0.0f;
        const float inv_lab = 1.0f / f_ls[tid];
        #pragma unroll
        for (int n = 0; n < NBIN_; n++) {
            const float vhl = f_hl[tid][n];
            cl += vhl;
            ca += f_ha[tid][n];
            s += (cl / (ca + 1e-16f)) * (vhl * inv_lab);
        }
        apq = s / (float)NBIN_;
    }
    if (tid < 32) {
        #pragma unroll
        for (int o = 16; o; o >>= 1) apq += __shfl_xor_sync(0xFFFFFFFFu, apq, o);
        if (tid == 0) {
            out[0] = apq / (float)B_;
            g_ticket = 0u;
        }
    }
}

extern "C" void kernel_launch(void* const* d_in, const int* in_sizes, int n_in,
                              void* d_out, int out_size) {
    const float* qX     = (const float*)d_in[0];
    const float* dXs    = (const float*)d_in[1];
    const int*   labels = (const int*)d_in[2];
    float*       out    = (float*)d_out;

    qap_fused<<<NBLK_, 256>>>(qX, dXs, labels, out);
}

// round 15
// speedup vs baseline: 1.0121x; 1.0121x over previous
#include <cuda_runtime.h>
#include <math.h>

#define B_    16
#define D_    100000
#define M_    128
#define NBIN_ 25
#define G_    27                  // blocks per batch -> 432 total = 3/SM (148 SMs)
#define TOTAL_ (B_ * G_)
#define NSLOT_ 27                 // padded: slot j == bin j-1; slots 0 and 26 are trash

// global accumulators — zero at module load; last block re-zeros them each
// run so every graph replay starts from identical state.
__device__ float    g_hla[B_][NBIN_];
__device__ float    g_hll[B_][NBIN_];
__device__ float    g_lsum[B_];
__device__ unsigned g_ticket;

__global__ void __launch_bounds__(256, 3)
qap_fused(const float* __restrict__ qX,
          const float* __restrict__ dXs,
          const int*   __restrict__ labels,
          float*       __restrict__ out) {
    const int b    = blockIdx.y;
    const int tid  = threadIdx.x;
    const int lane = tid & 31;
    const int warp = tid >> 5;
    const int e    = lane & 7;   // float4 slot within row
    const int g    = lane >> 3;  // doc within quad (0..3)

    // per-(warp,doc) private histograms: [warp][doc(8)][arr][NSLOT_]
    __shared__ float s_hist[8 * 8 * 2 * NSLOT_];   // 13.5 KB
    __shared__ float s_wl[8];
    __shared__ int   s_last;

    #pragma unroll
    for (int i = tid; i < 8 * 8 * 2 * NSLOT_; i += 256) s_hist[i] = 0.0f;
    __syncthreads();

    // query slices + 1/|q| via 8-lane group butterfly
    const float4* __restrict__ qf = reinterpret_cast<const float4*>(qX + b * M_);
    const float4 q0 = qf[e], q1 = qf[e + 8], q2 = qf[e + 16], q3 = qf[e + 24];
    float qs = q0.x*q0.x + q0.y*q0.y + q0.z*q0.z + q0.w*q0.w
             + q1.x*q1.x + q1.y*q1.y + q1.z*q1.z + q1.w*q1.w
             + q2.x*q2.x + q2.y*q2.y + q2.z*q2.z + q2.w*q2.w
             + q3.x*q3.x + q3.y*q3.y + q3.z*q3.z + q3.w*q3.w;
    qs += __shfl_xor_sync(0xFFFFFFFFu, qs, 4);
    qs += __shfl_xor_sync(0xFFFFFFFFu, qs, 2);
    qs += __shfl_xor_sync(0xFFFFFFFFu, qs, 1);
    const float inv_qn = rsqrtf(qs);

    const float4* __restrict__ dv = reinterpret_cast<const float4*>(dXs + (size_t)b * D_ * M_);
    const int*    __restrict__ lb = labels + b * D_;

    const int wid     = blockIdx.x * 8 + warp;
    const int stride8 = G_ * 8 * 8;      // 1728 docs per sweep
    const int docoff  = g + (e & 4);     // this lane's doc within the 8-doc chunk
    const int role    = e & 3;           // 0: ha[m0], 1: ha[m1], 2: hl[m0], 3: hl[m1]
    float* const hbase = s_hist + ((warp * 8 + docoff) * 2 + (role >> 1)) * NSLOT_
                       + (role & 1) + 1;
    float labcnt = 0.0f;

    // ---------------- software-pipelined main loop (8 docs/iter) ----------------
    int d0 = wid * 8;                    // < 1728 <= D_, every warp has work
    const float4* ra = dv + (size_t)(d0 + g) * 32;
    const float4* rb = ra + 4 * 32;
    float4 a0 = __ldcs(ra + e),      a1 = __ldcs(ra + e + 8);
    float4 a2 = __ldcs(ra + e + 16), a3 = __ldcs(ra + e + 24);
    float4 b0 = __ldcs(rb + e),      b1 = __ldcs(rb + e + 8);
    float4 b2 = __ldcs(rb + e + 16), b3 = __ldcs(rb + e + 24);
    int    lab = lb[d0 + docoff];

    while (d0 < D_) {
        const int dn   = d0 + stride8;
        const int dpre = (dn < D_) ? dn : 0;     // clamped prefetch (in-bounds, unused if done)
        const float4* rna = dv + (size_t)(dpre + g) * 32;
        const float4* rnb = rna + 4 * 32;

        // consume a-regs into sums, refill with next chunk's a-data
        float dota = q0.x*a0.x + q0.y*a0.y + q0.z*a0.z + q0.w*a0.w
                   + q1.x*a1.x + q1.y*a1.y + q1.z*a1.z + q1.w*a1.w
                   + q2.x*a2.x + q2.y*a2.y + q2.z*a2.z + q2.w*a2.w
                   + q3.x*a3.x + q3.y*a3.y + q3.z*a3.z + q3.w*a3.w;
        float nra  = a0.x*a0.x + a0.y*a0.y + a0.z*a0.z + a0.w*a0.w
                   + a1.x*a1.x + a1.y*a1.y + a1.z*a1.z + a1.w*a1.w
                   + a2.x*a2.x + a2.y*a2.y + a2.z*a2.z + a2.w*a2.w
                   + a3.x*a3.x + a3.y*a3.y + a3.z*a3.z + a3.w*a3.w;
        a0 = __ldcs(rna + e);      a1 = __ldcs(rna + e + 8);
        a2 = __ldcs(rna + e + 16); a3 = __ldcs(rna + e + 24);

        // consume b-regs, refill with next chunk's b-data
        float dotb = q0.x*b0.x + q0.y*b0.y + q0.z*b0.z + q0.w*b0.w
                   + q1.x*b1.x + q1.y*b1.y + q1.z*b1.z + q1.w*b1.w
                   + q2.x*b2.x + q2.y*b2.y + q2.z*b2.z + q2.w*b2.w
                   + q3.x*b3.x + q3.y*b3.y + q3.z*b3.z + q3.w*b3.w;
        float nrb  = b0.x*b0.x + b0.y*b0.y + b0.z*b0.z + b0.w*b0.w
                   + b1.x*b1.x + b1.y*b1.y + b1.z*b1.z + b1.w*b1.w
                   + b2.x*b2.x + b2.y*b2.y + b2.z*b2.z + b2.w*b2.w
                   + b3.x*b3.x + b3.y*b3.y + b3.z*b3.z + b3.w*b3.w;
        b0 = __ldcs(rnb + e);      b1 = __ldcs(rnb + e + 8);
        b2 = __ldcs(rnb + e + 16); b3 = __ldcs(rnb + e + 24);

        const int labcur = lab;
        lab = lb[dpre + docoff];

        // shuffles + epilogue run UNDER the next chunk's DRAM latency
        #pragma unroll
        for (int o = 4; o; o >>= 1) {
            dota += __shfl_xor_sync(0xFFFFFFFFu, dota, o);
            nra  += __shfl_xor_sync(0xFFFFFFFFu, nra,  o);
            dotb += __shfl_xor_sync(0xFFFFFFFFu, dotb, o);
            nrb  += __shfl_xor_sync(0xFFFFFFFFu, nrb,  o);
        }

        const float dt  = (e < 4) ? dota : dotb;
        const float nr  = (e < 4) ? nra  : nrb;
        const float sim = dt * rsqrtf(nr) * inv_qn;     // eps never binds (norms ~11)
        const float t   = (1.0f - sim) * 12.0f;
        const float mf  = floorf(t);
        const int   m0  = (int)mf;                      // in [-1, 24] for any fp edge
        const float fr  = t - mf;
        float w = (role & 1) ? fr : (1.0f - fr);
        if (role & 2) w *= (float)labcur;               // branchless label gate
        hbase[m0] += w;                                 // LDS+FADD+STS, race-free
        if (role == 0) labcnt += (float)labcur;         // doc counted once (e==0, e==4)

        d0 = dn;
    }

    #pragma unroll
    for (int o = 16; o; o >>= 1) labcnt += __shfl_xor_sync(0xFFFFFFFFu, labcnt, o);
    if (lane == 0) s_wl[warp] = labcnt;
    __syncthreads();

    // merge the 64 private copies (bins at slot n+1) into global accumulators
    for (int idx = tid; idx < 2 * NBIN_; idx += 256) {
        const int arr = idx / NBIN_, n = idx % NBIN_;
        float s = 0.0f;
        #pragma unroll
        for (int c = 0; c < 64; c++)
            s += s_hist[(c * 2 + arr) * NSLOT_ + n + 1];
        if (arr) atomicAdd(&g_hll[b][n], s);
        else     atomicAdd(&g_hla[b][n], s);
    }
    if (tid == 0) {
        float s = 0.0f;
        #pragma unroll
        for (int w = 0; w < 8; w++) s += s_wl[w];
        atomicAdd(&g_lsum[b], s);
    }

    __threadfence();
    __syncthreads();
    if (tid == 0) {
        unsigned prev = atomicAdd(&g_ticket, 1u);
        s_last = (prev == TOTAL_ - 1u);
    }
    __syncthreads();
    if (!s_last) return;

    // ---------------- last block: finalize + reset state ----------------
    __shared__ float f_hl[B_][NBIN_];
    __shared__ float f_ha[B_][NBIN_];
    __shared__ float f_ls[B_];

    for (int idx = tid; idx < B_ * NBIN_; idx += 256) {
        const int bb = idx / NBIN_, n = idx % NBIN_;
        f_hl[bb][n] = __ldcg(&g_hll[bb][n]);
        f_ha[bb][n] = __ldcg(&g_hla[bb][n]);
        g_hll[bb][n] = 0.0f;
        g_hla[bb][n] = 0.0f;
    }
    if (tid < B_) {
        f_ls[tid] = __ldcg(&g_lsum[tid]);
        g_lsum[tid] = 0.0f;
    }
    __syncthreads();

    float apq = 0.0f;
    if (tid < B_) {
        float cl = 0.0f, ca = 0.0f, s = 0.0f;
        const float inv_lab = 1.0f / f_ls[tid];
        #pragma unroll
        for (int n = 0; n < NBIN_; n++) {
            const float vhl = f_hl[tid][n];
            cl += vhl;
            ca += f_ha[tid][n];
            s += (cl / (ca + 1e-16f)) * (vhl * inv_lab);
        }
        apq = s / (float)NBIN_;
    }
    if (tid < 32) {
        #pragma unroll
        for (int o = 16; o; o >>= 1) apq += __shfl_xor_sync(0xFFFFFFFFu, apq, o);
        if (tid == 0) {
            out[0] = apq / (float)B_;
            g_ticket = 0u;
        }
    }
}

extern "C" void kernel_launch(void* const* d_in, const int* in_sizes, int n_in,
                              void* d_out, int out_size) {
    const float* qX     = (const float*)d_in[0];
    const float* dXs    = (const float*)d_in[1];
    const int*   labels = (const int*)d_in[2];
    float*       out    = (float*)d_out;

    qap_fused<<<dim3(G_, B_), 256>>>(qX, dXs, labels, out);
}

// round 16
// speedup vs baseline: 1.0135x; 1.0013x over previous
#include <cuda_runtime.h>
#include <math.h>

#define B_    16
#define D_    100000
#define M_    128
#define NBIN_ 25
#define G_    27                  // blocks per batch -> 432 total = 3/SM (148 SMs)
#define TOTAL_ (B_ * G_)
#define NSLOT_ 27                 // padded: slot j == bin j-1; slots 0 and 26 are trash

// global accumulators — zero at module load; last block re-zeros them each
// run so every graph replay starts from identical state.
__device__ float    g_hla[B_][NBIN_];
__device__ float    g_hll[B_][NBIN_];
__device__ float    g_lsum[B_];
__device__ unsigned g_ticket;

__global__ void __launch_bounds__(256, 3)
qap_fused(const float* __restrict__ qX,
          const float* __restrict__ dXs,
          const int*   __restrict__ labels,
          float*       __restrict__ out) {
    const int b    = blockIdx.y;
    const int tid  = threadIdx.x;
    const int lane = tid & 31;
    const int warp = tid >> 5;
    const int e    = lane & 7;   // float4 slot within row
    const int g    = lane >> 3;  // doc within quad (0..3)

    // per-(warp,doc) private histograms: [warp][doc(8)][arr][NSLOT_]
    __shared__ float s_hist[8 * 8 * 2 * NSLOT_];   // 13.5 KB
    __shared__ float s_wl[8];
    __shared__ int   s_last;

    #pragma unroll
    for (int i = tid; i < 8 * 8 * 2 * NSLOT_; i += 256) s_hist[i] = 0.0f;
    __syncthreads();

    // query slices + 1/|q| via 8-lane group butterfly
    const float4* __restrict__ qf = reinterpret_cast<const float4*>(qX + b * M_);
    const float4 q0 = qf[e], q1 = qf[e + 8], q2 = qf[e + 16], q3 = qf[e + 24];
    float qs = q0.x*q0.x + q0.y*q0.y + q0.z*q0.z + q0.w*q0.w
             + q1.x*q1.x + q1.y*q1.y + q1.z*q1.z + q1.w*q1.w
             + q2.x*q2.x + q2.y*q2.y + q2.z*q2.z + q2.w*q2.w
             + q3.x*q3.x + q3.y*q3.y + q3.z*q3.z + q3.w*q3.w;
    qs += __shfl_xor_sync(0xFFFFFFFFu, qs, 4);
    qs += __shfl_xor_sync(0xFFFFFFFFu, qs, 2);
    qs += __shfl_xor_sync(0xFFFFFFFFu, qs, 1);
    const float inv_qn = rsqrtf(qs);

    const float4* __restrict__ dv = reinterpret_cast<const float4*>(dXs + (size_t)b * D_ * M_);
    const int*    __restrict__ lb = labels + b * D_;

    const int wid     = blockIdx.x * 8 + warp;
    const int stride8 = G_ * 8 * 8;      // 1728 docs per sweep
    const int docoff  = g + (e & 4);     // this lane's doc within the 8-doc chunk
    const int role    = e & 3;           // 0: ha[m0], 1: ha[m1], 2: hl[m0], 3: hl[m1]
    float* const hbase = s_hist + ((warp * 8 + docoff) * 2 + (role >> 1)) * NSLOT_
                       + (role & 1) + 1;
    float labcnt = 0.0f;

    // ---------------- software-pipelined main loop (8 docs/iter) ----------------
    int d0 = wid * 8;                    // < 1728 <= D_, every warp has work
    const float4* ra = dv + (size_t)(d0 + g) * 32;
    const float4* rb = ra + 4 * 32;
    float4 a0 = __ldcs(ra + e),      a1 = __ldcs(ra + e + 8);
    float4 a2 = __ldcs(ra + e + 16), a3 = __ldcs(ra + e + 24);
    float4 b0 = __ldcs(rb + e),      b1 = __ldcs(rb + e + 8);
    float4 b2 = __ldcs(rb + e + 16), b3 = __ldcs(rb + e + 24);
    int    lab = lb[d0 + docoff];

    while (d0 < D_) {
        const int dn   = d0 + stride8;
        const int dpre = (dn < D_) ? dn : 0;     // clamped prefetch (in-bounds, unused if done)
        const float4* rna = dv + (size_t)(dpre + g) * 32;
        const float4* rnb = rna + 4 * 32;

        // consume a-regs into sums, refill with next chunk's a-data
        float dota = q0.x*a0.x + q0.y*a0.y + q0.z*a0.z + q0.w*a0.w
                   + q1.x*a1.x + q1.y*a1.y + q1.z*a1.z + q1.w*a1.w
                   + q2.x*a2.x + q2.y*a2.y + q2.z*a2.z + q2.w*a2.w
                   + q3.x*a3.x + q3.y*a3.y + q3.z*a3.z + q3.w*a3.w;
        float nra  = a0.x*a0.x + a0.y*a0.y + a0.z*a0.z + a0.w*a0.w
                   + a1.x*a1.x + a1.y*a1.y + a1.z*a1.z + a1.w*a1.w
                   + a2.x*a2.x + a2.y*a2.y + a2.z*a2.z + a2.w*a2.w
                   + a3.x*a3.x + a3.y*a3.y + a3.z*a3.z + a3.w*a3.w;
        a0 = __ldcs(rna + e);      a1 = __ldcs(rna + e + 8);
        a2 = __ldcs(rna + e + 16); a3 = __ldcs(rna + e + 24);

        // consume b-regs, refill with next chunk's b-data
        float dotb = q0.x*b0.x + q0.y*b0.y + q0.z*b0.z + q0.w*b0.w
                   + q1.x*b1.x + q1.y*b1.y + q1.z*b1.z + q1.w*b1.w
                   + q2.x*b2.x + q2.y*b2.y + q2.z*b2.z + q2.w*b2.w
                   + q3.x*b3.x + q3.y*b3.y + q3.z*b3.z + q3.w*b3.w;
        float nrb  = b0.x*b0.x + b0.y*b0.y + b0.z*b0.z + b0.w*b0.w
                   + b1.x*b1.x + b1.y*b1.y + b1.z*b1.z + b1.w*b1.w
                   + b2.x*b2.x + b2.y*b2.y + b2.z*b2.z + b2.w*b2.w
                   + b3.x*b3.x + b3.y*b3.y + b3.z*b3.z + b3.w*b3.w;
        b0 = __ldcs(rnb + e);      b1 = __ldcs(rnb + e + 8);
        b2 = __ldcs(rnb + e + 16); b3 = __ldcs(rnb + e + 24);

        const int labcur = lab;
        lab = lb[dpre + docoff];

        // shuffles + epilogue run UNDER the next chunk's DRAM latency
        #pragma unroll
        for (int o = 4; o; o >>= 1) {
            dota += __shfl_xor_sync(0xFFFFFFFFu, dota, o);
            nra  += __shfl_xor_sync(0xFFFFFFFFu, nra,  o);
            dotb += __shfl_xor_sync(0xFFFFFFFFu, dotb, o);
            nrb  += __shfl_xor_sync(0xFFFFFFFFu, nrb,  o);
        }

        const float dt  = (e < 4) ? dota : dotb;
        const float nr  = (e < 4) ? nra  : nrb;
        const float sim = dt * rsqrtf(nr) * inv_qn;     // eps never binds (norms ~11)
        const float t   = (1.0f - sim) * 12.0f;
        const float mf  = floorf(t);
        const int   m0  = (int)mf;                      // in [-1, 24] for any fp edge
        const float fr  = t - mf;
        float w = (role & 1) ? fr : (1.0f - fr);
        if (role & 2) w *= (float)labcur;               // branchless label gate
        hbase[m0] += w;                                 // LDS+FADD+STS, race-free
        if (role == 0) labcnt += (float)labcur;         // doc counted once (e==0, e==4)

        d0 = dn;
    }

    #pragma unroll
    for (int o = 16; o; o >>= 1) labcnt += __shfl_xor_sync(0xFFFFFFFFu, labcnt, o);
    if (lane == 0) s_wl[warp] = labcnt;
    __syncthreads();

    // merge the 64 private copies (bins at slot n+1) into global accumulators
    for (int idx = tid; idx < 2 * NBIN_; idx += 256) {
        const int arr = idx / NBIN_, n = idx % NBIN_;
        float s = 0.0f;
        #pragma unroll
        for (int c = 0; c < 64; c++)
            s += s_hist[(c * 2 + arr) * NSLOT_ + n + 1];
        if (arr) atomicAdd(&g_hll[b][n], s);
        else     atomicAdd(&g_hla[b][n], s);
    }
    if (tid == 0) {
        float s = 0.0f;
        #pragma unroll
        for (int w = 0; w < 8; w++) s += s_wl[w];
        atomicAdd(&g_lsum[b], s);
    }

    __threadfence();
    __syncthreads();
    if (tid == 0) {
        unsigned prev = atomicAdd(&g_ticket, 1u);
        s_last = (prev == TOTAL_ - 1u);
    }
    __syncthreads();
    if (!s_last) return;

    // ---------------- last block: finalize + reset state ----------------
    __shared__ float f_hl[B_][NBIN_];
    __shared__ float f_ha[B_][NBIN_];
    __shared__ float f_ls[B_];

    for (int idx = tid; idx < B_ * NBIN_; idx += 256) {
        const int bb = idx / NBIN_, n = idx % NBIN_;
        f_hl[bb][n] = __ldcg(&g_hll[bb][n]);
        f_ha[bb][n] = __ldcg(&g_hla[bb][n]);
        g_hll[bb][n] = 0.0f;
        g_hla[bb][n] = 0.0f;
    }
    if (tid < B_) {
        f_ls[tid] = __ldcg(&g_lsum[tid]);
        g_lsum[tid] = 0.0f;
    }
    __syncthreads();

    float apq = 0.0f;
    if (tid < B_) {
        float cl = 0.0f, ca = 0.0f, s = 0.0f;
        const float inv_lab = 1.0f / f_ls[tid];
        #pragma unroll
        for (int n = 0; n < NBIN_; n++) {
            const float vhl = f_hl[tid][n];
            cl += vhl;
            ca += f_ha[tid][n];
            s += (cl / (ca + 1e-16f)) * (vhl * inv_lab);
        }
        apq = s / (float)NBIN_;
    }
    if (tid < 32) {
        #pragma unroll
        for (int o = 16; o; o >>= 1) apq += __shfl_xor_sync(0xFFFFFFFFu, apq, o);
        if (tid == 0) {
            out[0] = apq / (float)B_;
            g_ticket = 0u;
        }
    }
}

extern "C" void kernel_launch(void* const* d_in, const int* in_sizes, int n_in,
                              void* d_out, int out_size) {
    const float* qX     = (const float*)d_in[0];
    const float* dXs    = (const float*)d_in[1];
    const int*   labels = (const int*)d_in[2];
    float*       out    = (float*)d_out;

    qap_fused<<<dim3(G_, B_), 256>>>(qX, dXs, labels, out);
}